// round 15
// baseline (speedup 1.0000x reference)
#include <cuda_runtime.h>
#include <cuda_fp16.h>
#include <cstdint>

// Problem constants
#define T_SEQ 2048
#define CDIM  512
#define BDIM  2
#define HNUM  8
#define HD    64
#define BT    (BDIM * T_SEQ)

// ---------------- scratch (device globals; no allocation allowed) ----------
__device__ __half g_xpad [BDIM * (T_SEQ + 2) * CDIM];
__device__ __half g_wcT  [CDIM * 3 * CDIM];     // [o][k*512+i]
__device__ __half g_qkvT [3 * CDIM * CDIM];
__device__ __half g_projT[CDIM * CDIM];
__device__ __half g_ffn1T[2 * CDIM * CDIM];
__device__ __half g_ffn2T[CDIM * 2 * CDIM];
__device__ __half g_convh[2 * BT * CDIM];       // 2 split-K partials
__device__ __half g_x1h  [BT * CDIM];
__device__ __half g_x2h  [BT * CDIM];
__device__ __half g_qkvh [BT * 3 * CDIM];
__device__ __half g_attnh[BT * CDIM];
__device__ __half g_projh[2 * BT * CDIM];       // 2 split-K partials
__device__ __half g_ffnhh[BT * 2 * CDIM];
__device__ __half g_ffn2h[2 * BT * CDIM];       // 2 split-K partials

// ---------------- small prep kernels ---------------------------------------
__global__ void pad_kernel(const float* __restrict__ x, __half* __restrict__ xpad) {
    int idx = blockIdx.x * blockDim.x + threadIdx.x;
    const int total = BDIM * (T_SEQ + 2) * CDIM;
    if (idx >= total) return;
    int c = idx % CDIM;
    int t = (idx / CDIM) % (T_SEQ + 2);
    int b = idx / (CDIM * (T_SEQ + 2));
    float v = (t < 2) ? 0.0f : x[((long long)b * T_SEQ + (t - 2)) * CDIM + c];
    xpad[idx] = __float2half_rn(v);
}

// all weight preps in one launch: z=0..3 tiled transposes, z=4 conv gather.
__global__ void prep_weights_kernel(const float* __restrict__ qkv_w,
                                    const float* __restrict__ proj_w,
                                    const float* __restrict__ ffn_w1,
                                    const float* __restrict__ ffn_w2,
                                    const float* __restrict__ conv_w,
                                    __half* __restrict__ qkvT,
                                    __half* __restrict__ projT,
                                    __half* __restrict__ ffn1T,
                                    __half* __restrict__ ffn2T,
                                    __half* __restrict__ wcT) {
    if (blockIdx.z == 4) {
        int r = blockIdx.x * 32 + threadIdx.x;       // 0..1535
        int o0 = blockIdx.y * 32;
        if (o0 >= CDIM) return;
        int k = r / CDIM;
        int i = r % CDIM;
        #pragma unroll
        for (int j = 0; j < 32; j += 8) {
            int o = o0 + threadIdx.y + j;
            wcT[(long long)o * (3 * CDIM) + r] =
                __float2half_rn(conv_w[((long long)o * CDIM + i) * 3 + k]);
        }
        return;
    }
    const float* in;
    __half* outp;
    int K, N;
    switch (blockIdx.z) {
        case 0: in = qkv_w;  outp = qkvT;  K = 512;  N = 1536; break;
        case 1: in = proj_w; outp = projT; K = 512;  N = 512;  break;
        case 2: in = ffn_w1; outp = ffn1T; K = 512;  N = 1024; break;
        default: in = ffn_w2; outp = ffn2T; K = 1024; N = 512; break;
    }
    int bx = blockIdx.x * 32, by = blockIdx.y * 32;
    if (bx >= N || by >= K) return;

    __shared__ float tile[32][33];
    #pragma unroll
    for (int j = 0; j < 32; j += 8)
        tile[threadIdx.y + j][threadIdx.x] =
            in[(long long)(by + threadIdx.y + j) * N + bx + threadIdx.x];
    __syncthreads();
    #pragma unroll
    for (int j = 0; j < 32; j += 8)
        outp[(long long)(bx + threadIdx.y + j) * K + by + threadIdx.x] =
            __float2half_rn(tile[threadIdx.x][threadIdx.y + j]);
}

// ---------------- fused residual add + LayerNorm (fp16 dataflow) -------------
// 2 rows/block, 256 threads. A_FP32: a fp32 else fp16. OUT_FP32: out fp32 else
// fp16. R2: r has a second split-K partial at offset BT*CDIM. Stats in fp32.
template <int A_FP32, int OUT_FP32, int R2>
__global__ void add_ln_kernel(const void* __restrict__ av, const __half* __restrict__ r,
                              const float* __restrict__ g, const float* __restrict__ be,
                              void* __restrict__ outv) {
    __shared__ float sh[8];
    const int tid = threadIdx.x;
    const int half = tid >> 7;
    const int t2 = tid & 127;
    const long long row = (long long)blockIdx.x * 2 + half;

    float a0, a1, a2, a3;
    if (A_FP32) {
        const float4 va = ((const float4*)((const float*)av + row * CDIM))[t2];
        a0 = va.x; a1 = va.y; a2 = va.z; a3 = va.w;
    } else {
        uint2 u = *(const uint2*)((const __half*)av + row * CDIM + t2 * 4);
        __half2 h0 = *(__half2*)&u.x;
        __half2 h1 = *(__half2*)&u.y;
        a0 = __low2float(h0); a1 = __high2float(h0);
        a2 = __low2float(h1); a3 = __high2float(h1);
    }
    float r0, r1, r2, r3;
    {
        uint2 u = *(const uint2*)(r + row * CDIM + t2 * 4);
        __half2 h0 = *(__half2*)&u.x;
        __half2 h1 = *(__half2*)&u.y;
        r0 = __low2float(h0); r1 = __high2float(h0);
        r2 = __low2float(h1); r3 = __high2float(h1);
    }
    if (R2) {
        uint2 u = *(const uint2*)(r + (long long)BT * CDIM + row * CDIM + t2 * 4);
        __half2 h0 = *(__half2*)&u.x;
        __half2 h1 = *(__half2*)&u.y;
        r0 += __low2float(h0); r1 += __high2float(h0);
        r2 += __low2float(h1); r3 += __high2float(h1);
    }
    float x0 = a0 + r0, x1 = a1 + r1, x2 = a2 + r2, x3 = a3 + r3;

    float s = x0 + x1 + x2 + x3;
    #pragma unroll
    for (int o = 16; o; o >>= 1) s += __shfl_xor_sync(0xffffffffu, s, o);
    if ((t2 & 31) == 0) sh[half * 4 + (t2 >> 5)] = s;
    __syncthreads();
    float mean = (sh[half * 4] + sh[half * 4 + 1] + sh[half * 4 + 2] + sh[half * 4 + 3])
                 * (1.0f / CDIM);
    __syncthreads();

    float d0 = x0 - mean, d1 = x1 - mean, d2 = x2 - mean, d3 = x3 - mean;
    float ss = d0 * d0 + d1 * d1 + d2 * d2 + d3 * d3;
    #pragma unroll
    for (int o = 16; o; o >>= 1) ss += __shfl_xor_sync(0xffffffffu, ss, o);
    if ((t2 & 31) == 0) sh[half * 4 + (t2 >> 5)] = ss;
    __syncthreads();
    float var = (sh[half * 4] + sh[half * 4 + 1] + sh[half * 4 + 2] + sh[half * 4 + 3])
                * (1.0f / CDIM);
    float rs = rsqrtf(var + 1e-5f);

    float4 vg = ((const float4*)g)[t2];
    float4 vb = ((const float4*)be)[t2];
    float o0 = d0 * rs * vg.x + vb.x;
    float o1 = d1 * rs * vg.y + vb.y;
    float o2 = d2 * rs * vg.z + vb.z;
    float o3 = d3 * rs * vg.w + vb.w;

    if (OUT_FP32) {
        ((float4*)((float*)outv + row * CDIM))[t2] = make_float4(o0, o1, o2, o3);
    } else {
        __half2 h0 = __floats2half2_rn(o0, o1);
        __half2 h1 = __floats2half2_rn(o2, o3);
        *(uint2*)((__half*)outv + row * CDIM + t2 * 4) =
            make_uint2(*(uint32_t*)&h0, *(uint32_t*)&h1);
    }
}

// ---------------- mma / ldmatrix helpers -------------------------------------
__device__ __forceinline__ void mma_f16(float c[4], uint32_t a0, uint32_t a1,
                                        uint32_t a2, uint32_t a3,
                                        uint32_t b0, uint32_t b1) {
    asm volatile(
        "mma.sync.aligned.m16n8k16.row.col.f32.f16.f16.f32 "
        "{%0,%1,%2,%3}, {%4,%5,%6,%7}, {%8,%9}, {%0,%1,%2,%3};"
        : "+f"(c[0]), "+f"(c[1]), "+f"(c[2]), "+f"(c[3])
        : "r"(a0), "r"(a1), "r"(a2), "r"(a3), "r"(b0), "r"(b1));
}

__device__ __forceinline__ void ldsm_x4(uint32_t& r0, uint32_t& r1,
                                        uint32_t& r2, uint32_t& r3, uint32_t addr) {
    asm volatile("ldmatrix.sync.aligned.m8n8.x4.shared.b16 {%0,%1,%2,%3}, [%4];"
                 : "=r"(r0), "=r"(r1), "=r"(r2), "=r"(r3) : "r"(addr));
}

#define CP16(dst, src) \
    asm volatile("cp.async.cg.shared.global [%0], [%1], 16;" :: "r"(dst), "l"(src))
#define CP_COMMIT() asm volatile("cp.async.commit_group;")
#define CP_WAIT(n)  asm volatile("cp.async.wait_group %0;" :: "n"(n))

// ---------------- fp16 TC GEMM with optional split-K -------------------------
// blockIdx.z = batch * NSPLIT + split. Each split computes K-sub-range
// [split*K, (split+1)*K) and writes its partial into C + split*splitC.
// Bias added by split 0 only. ACT==2 (relu) only valid with NSPLIT==1.
#define RBYTES 144
#define ABYTES (128 * RBYTES)
#define STG_BYTES (2 * ABYTES)
#define GSTAGES 3
#define GEMM_SMEM (GSTAGES * STG_BYTES)   // 110592 B

__device__ __forceinline__ void load_tile_h(uint32_t sbase,
                                            const __half* __restrict__ gA, int lda,
                                            const __half* __restrict__ gB, int ldb,
                                            int tid) {
    #pragma unroll
    for (int i = 0; i < 4; i++) {
        int u = tid + i * 256;
        int row = u >> 3, c = u & 7;
        CP16(sbase + row * RBYTES + c * 16, gA + (long long)row * lda + c * 8);
    }
    #pragma unroll
    for (int i = 0; i < 4; i++) {
        int u = tid + i * 256;
        int row = u >> 3, c = u & 7;
        CP16(sbase + ABYTES + row * RBYTES + c * 16, gB + (long long)row * ldb + c * 8);
    }
}

template <int ACT, int NSPLIT>
__global__ __launch_bounds__(256, 2)
void hgemm_kernel(const __half* __restrict__ A, int lda, long long strideA,
                  const __half* __restrict__ Bt, int ldb,
                  __half* __restrict__ C, int ldc, long long strideC,
                  long long splitC,
                  int K, const float* __restrict__ bias) {
    const int split = (NSPLIT > 1) ? (blockIdx.z % NSPLIT) : 0;
    const int batch = (NSPLIT > 1) ? (blockIdx.z / NSPLIT) : blockIdx.z;
    A += (long long)batch * strideA + (long long)split * K;
    Bt += (long long)split * K;
    C += (long long)batch * strideC + (long long)split * splitC;
    const bool addBias = (ACT > 0) && (split == 0);

    extern __shared__ __half smh[];
    const int tid = threadIdx.x;
    const int lane = tid & 31;
    const int warp = tid >> 5;
    const int warpM = warp >> 2;
    const int warpN = warp & 3;
    const int tg = lane & 3;
    const int gid = lane >> 2;

    uint32_t sbase;
    asm("{ .reg .u64 t; cvta.to.shared.u64 t, %1; cvt.u32.u64 %0, t; }"
        : "=r"(sbase) : "l"(smh));

    float acc[4][4][4];
    #pragma unroll
    for (int i = 0; i < 4; i++)
        #pragma unroll
        for (int j = 0; j < 4; j++)
            #pragma unroll
            for (int q = 0; q < 4; q++) acc[i][j][q] = 0.0f;

    const int aRow = (lane & 15);
    const int aKoff = (lane >> 4) << 4;
    const int bLocal = lane & 7;
    const int bSel = (lane >> 3) & 3;
    const int bNsub = (bSel >> 1);
    const int bKoff = (bSel & 1) * 16;

    const __half* Ag = A + (long long)blockIdx.y * 128 * lda;
    const __half* Bg = Bt + (long long)blockIdx.x * 128 * ldb;
    const int ntile = K >> 6;

    #pragma unroll
    for (int p = 0; p < GSTAGES - 1; p++) {
        load_tile_h(sbase + p * STG_BYTES, Ag + p * 64, lda, Bg + p * 64, ldb, tid);
        CP_COMMIT();
    }

    for (int t = 0; t < ntile; t++) {
        CP_WAIT(GSTAGES - 2);
        __syncthreads();

        int f = t + GSTAGES - 1;
        if (f < ntile)
            load_tile_h(sbase + (f % GSTAGES) * STG_BYTES, Ag + f * 64, lda,
                        Bg + f * 64, ldb, tid);
        CP_COMMIT();

        const uint32_t Ab = sbase + (t % GSTAGES) * STG_BYTES;
        const uint32_t Bb = Ab + ABYTES;

        #pragma unroll
        for (int ks = 0; ks < 4; ks++) {
            const int kbB = ks * 32;
            uint32_t af[4][4], bf[4][2];
            #pragma unroll
            for (int mi = 0; mi < 4; mi++) {
                uint32_t addr = Ab + (warpM * 64 + mi * 16 + aRow) * RBYTES + kbB + aKoff;
                ldsm_x4(af[mi][0], af[mi][1], af[mi][2], af[mi][3], addr);
            }
            #pragma unroll
            for (int p = 0; p < 2; p++) {
                uint32_t addr = Bb + (warpN * 32 + (2 * p + bNsub) * 8 + bLocal) * RBYTES
                                + kbB + bKoff;
                ldsm_x4(bf[2 * p][0], bf[2 * p][1], bf[2 * p + 1][0], bf[2 * p + 1][1], addr);
            }
            #pragma unroll
            for (int mi = 0; mi < 4; mi++)
                #pragma unroll
                for (int ni = 0; ni < 4; ni++)
                    mma_f16(acc[mi][ni], af[mi][0], af[mi][1], af[mi][2], af[mi][3],
                            bf[ni][0], bf[ni][1]);
        }
        __syncthreads();
    }

    const int mbase = blockIdx.y * 128 + warpM * 64;
    const int nbase = blockIdx.x * 128 + warpN * 32;
    #pragma unroll
    for (int ni = 0; ni < 4; ni++) {
        int c0 = nbase + ni * 8 + tg * 2;
        float bv0 = 0.0f, bv1 = 0.0f;
        if (addBias) { bv0 = bias[c0]; bv1 = bias[c0 + 1]; }
        #pragma unroll
        for (int mi = 0; mi < 4; mi++) {
            int r0 = mbase + mi * 16 + gid;
            float v00 = acc[mi][ni][0] + bv0;
            float v01 = acc[mi][ni][1] + bv1;
            float v10 = acc[mi][ni][2] + bv0;
            float v11 = acc[mi][ni][3] + bv1;
            if (ACT == 2) {
                v00 = fmaxf(v00, 0.0f); v01 = fmaxf(v01, 0.0f);
                v10 = fmaxf(v10, 0.0f); v11 = fmaxf(v11, 0.0f);
            }
            *(__half2*)(C + (long long)r0 * ldc + c0) = __floats2half2_rn(v00, v01);
            *(__half2*)(C + (long long)(r0 + 8) * ldc + c0) = __floats2half2_rn(v10, v11);
        }
    }
}

// ---------------- fp16 flash attention (R12-exact: BQ=64, unnormalized exp) --
#define KS_STRIDE 72
#define VT_STRIDE 76

__global__ __launch_bounds__(128)
void flash_attn_h_kernel(const __half* __restrict__ qkv, __half* __restrict__ out) {
    __shared__ __half Ks[64 * KS_STRIDE];
    __shared__ __half Vt[64 * VT_STRIDE];

    const int qb = (gridDim.x - 1) - blockIdx.x;
    const int bh = blockIdx.y;
    const int b = bh >> 3, h = bh & 7;
    const int tid = threadIdx.x;
    const int lane = tid & 31;
    const int warp = tid >> 5;
    const int g = lane >> 2;
    const int t = lane & 3;
    const long long rstride = 3 * CDIM;

    const __half* q0 = qkv + ((long long)(b * T_SEQ + qb * 64 + warp * 16)) * rstride + h * HD;
    const __half2 scale = __float2half2_rn(0.125f);
    uint32_t qf[4][4];
    #pragma unroll
    for (int ks = 0; ks < 4; ks++) {
        __half2 v0 = __hmul2(*(const __half2*)(q0 + (long long)g * rstride + ks * 16 + 2 * t), scale);
        __half2 v1 = __hmul2(*(const __half2*)(q0 + (long long)(g + 8) * rstride + ks * 16 + 2 * t), scale);
        __half2 v2 = __hmul2(*(const __half2*)(q0 + (long long)g * rstride + ks * 16 + 8 + 2 * t), scale);
        __half2 v3 = __hmul2(*(const __half2*)(q0 + (long long)(g + 8) * rstride + ks * 16 + 8 + 2 * t), scale);
        qf[ks][0] = *(uint32_t*)&v0;
        qf[ks][1] = *(uint32_t*)&v1;
        qf[ks][2] = *(uint32_t*)&v2;
        qf[ks][3] = *(uint32_t*)&v3;
    }

    float o[8][4];
    #pragma unroll
    for (int ni = 0; ni < 8; ni++)
        #pragma unroll
        for (int q = 0; q < 4; q++) o[ni][q] = 0.0f;
    float ls0 = 0.0f, ls1 = 0.0f;

    const int row0 = qb * 64 + warp * 16 + g;
    const int row1 = row0 + 8;

    for (int kb = 0; kb <= qb; kb++) {
        const __half* kbase = qkv + ((long long)(b * T_SEQ + kb * 64)) * rstride + CDIM + h * HD;
        const __half* vbase = kbase + CDIM;

        #pragma unroll
        for (int i = 0; i < 4; i++) {
            int u = tid + i * 128;
            int r = u >> 3, c = u & 7;
            *(uint4*)&Ks[r * KS_STRIDE + c * 8] =
                *(const uint4*)(kbase + (long long)r * rstride + c * 8);
        }
        #pragma unroll
        for (int i = 0; i < 2; i++) {
            int u = tid + i * 128;
            int kp = u >> 3, d8 = u & 7;
            uint4 va = *(const uint4*)(vbase + (long long)(2 * kp) * rstride + d8 * 8);
            uint4 vb = *(const uint4*)(vbase + (long long)(2 * kp + 1) * rstride + d8 * 8);
            const __half* ah = (const __half*)&va;
            const __half* bhp = (const __half*)&vb;
            #pragma unroll
            for (int j = 0; j < 8; j++)
                *(__half2*)&Vt[(d8 * 8 + j) * VT_STRIDE + 2 * kp] =
                    __halves2half2(ah[j], bhp[j]);
        }
        __syncthreads();

        float s[8][4];
        #pragma unroll
        for (int ni = 0; ni < 8; ni++) {
            s[ni][0] = s[ni][1] = s[ni][2] = s[ni][3] = 0.0f;
            const __half* kr = &Ks[(ni * 8 + g) * KS_STRIDE];
            #pragma unroll
            for (int ks = 0; ks < 4; ks++) {
                uint32_t b0 = *(const uint32_t*)(kr + ks * 16 + 2 * t);
                uint32_t b1 = *(const uint32_t*)(kr + ks * 16 + 8 + 2 * t);
                mma_f16(s[ni], qf[ks][0], qf[ks][1], qf[ks][2], qf[ks][3], b0, b1);
            }
        }

        if (kb == qb) {
            #pragma unroll
            for (int ni = 0; ni < 8; ni++) {
                int col = kb * 64 + ni * 8 + 2 * t;
                if (col > row0)     s[ni][0] = -1e30f;
                if (col + 1 > row0) s[ni][1] = -1e30f;
                if (col > row1)     s[ni][2] = -1e30f;
                if (col + 1 > row1) s[ni][3] = -1e30f;
            }
        }

        uint32_t pf[4][4];
        #pragma unroll
        for (int j = 0; j < 4; j++) {
            float p00 = __expf(s[2 * j][0]);
            float p01 = __expf(s[2 * j][1]);
            float p02 = __expf(s[2 * j][2]);
            float p03 = __expf(s[2 * j][3]);
            float p10 = __expf(s[2 * j + 1][0]);
            float p11 = __expf(s[2 * j + 1][1]);
            float p12 = __expf(s[2 * j + 1][2]);
            float p13 = __expf(s[2 * j + 1][3]);
            ls0 += p00 + p01 + p10 + p11;
            ls1 += p02 + p03 + p12 + p13;
            __half2 h0 = __floats2half2_rn(p00, p01);
            __half2 h1 = __floats2half2_rn(p02, p03);
            __half2 h2 = __floats2half2_rn(p10, p11);
            __half2 h3 = __floats2half2_rn(p12, p13);
            pf[j][0] = *(uint32_t*)&h0;
            pf[j][1] = *(uint32_t*)&h1;
            pf[j][2] = *(uint32_t*)&h2;
            pf[j][3] = *(uint32_t*)&h3;
        }

        #pragma unroll
        for (int ni = 0; ni < 8; ni++) {
            const __half* vr = &Vt[(ni * 8 + g) * VT_STRIDE];
            #pragma unroll
            for (int j = 0; j < 4; j++) {
                uint32_t b0 = *(const uint32_t*)(vr + j * 16 + 2 * t);
                uint32_t b1 = *(const uint32_t*)(vr + j * 16 + 8 + 2 * t);
                mma_f16(o[ni], pf[j][0], pf[j][1], pf[j][2], pf[j][3], b0, b1);
            }
        }
        __syncthreads();
    }

    ls0 += __shfl_xor_sync(0xffffffffu, ls0, 1);
    ls0 += __shfl_xor_sync(0xffffffffu, ls0, 2);
    ls1 += __shfl_xor_sync(0xffffffffu, ls1, 1);
    ls1 += __shfl_xor_sync(0xffffffffu, ls1, 2);
    float inv0 = 1.0f / ls0, inv1 = 1.0f / ls1;
    __half* obase = out + ((long long)(b * T_SEQ)) * CDIM + h * HD;
    #pragma unroll
    for (int ni = 0; ni < 8; ni++) {
        int col = ni * 8 + 2 * t;
        *(__half2*)(obase + (long long)row0 * CDIM + col) =
            __floats2half2_rn(o[ni][0] * inv0, o[ni][1] * inv0);
        *(__half2*)(obase + (long long)row1 * CDIM + col) =
            __floats2half2_rn(o[ni][2] * inv1, o[ni][3] * inv1);
    }
}

// ---------------- launch -----------------------------------------------------
extern "C" void kernel_launch(void* const* d_in, const int* in_sizes, int n_in,
                              void* d_out, int out_size) {
    const float* x      = (const float*)d_in[0];
    const float* conv_w = (const float*)d_in[1];
    const float* conv_b = (const float*)d_in[2];
    const float* g1     = (const float*)d_in[3];
    const float* b1     = (const float*)d_in[4];
    const float* qkv_w  = (const float*)d_in[5];
    const float* qkv_b  = (const float*)d_in[6];
    const float* proj_w = (const float*)d_in[7];
    const float* proj_b = (const float*)d_in[8];
    const float* g2     = (const float*)d_in[9];
    const float* b2     = (const float*)d_in[10];
    const float* ffn_w1 = (const float*)d_in[11];
    const float* ffn_b1 = (const float*)d_in[12];
    const float* ffn_w2 = (const float*)d_in[13];
    const float* ffn_b2 = (const float*)d_in[14];
    const float* g3     = (const float*)d_in[15];
    const float* b3     = (const float*)d_in[16];
    float* out = (float*)d_out;

    __half *xpad, *wcT, *qkvT, *projT, *ffn1T, *ffn2T;
    __half *convh, *x1h, *x2h, *qkvh, *attnh, *projh, *ffnhh, *ffn2h;
    cudaGetSymbolAddress((void**)&xpad,  g_xpad);
    cudaGetSymbolAddress((void**)&wcT,   g_wcT);
    cudaGetSymbolAddress((void**)&qkvT,  g_qkvT);
    cudaGetSymbolAddress((void**)&projT, g_projT);
    cudaGetSymbolAddress((void**)&ffn1T, g_ffn1T);
    cudaGetSymbolAddress((void**)&ffn2T, g_ffn2T);
    cudaGetSymbolAddress((void**)&convh, g_convh);
    cudaGetSymbolAddress((void**)&x1h,   g_x1h);
    cudaGetSymbolAddress((void**)&x2h,   g_x2h);
    cudaGetSymbolAddress((void**)&qkvh,  g_qkvh);
    cudaGetSymbolAddress((void**)&attnh, g_attnh);
    cudaGetSymbolAddress((void**)&projh, g_projh);
    cudaGetSymbolAddress((void**)&ffnhh, g_ffnhh);
    cudaGetSymbolAddress((void**)&ffn2h, g_ffn2h);

    cudaFuncSetAttribute(hgemm_kernel<1, 1>,
                         cudaFuncAttributeMaxDynamicSharedMemorySize, GEMM_SMEM);
    cudaFuncSetAttribute(hgemm_kernel<1, 2>,
                         cudaFuncAttributeMaxDynamicSharedMemorySize, GEMM_SMEM);
    cudaFuncSetAttribute(hgemm_kernel<2, 1>,
                         cudaFuncAttributeMaxDynamicSharedMemorySize, GEMM_SMEM);

    const long long HBUF = (long long)BT * CDIM;

    {
        int total = BDIM * (T_SEQ + 2) * CDIM;
        pad_kernel<<<(total + 255) / 256, 256>>>(x, xpad);
    }
    prep_weights_kernel<<<dim3(48, 32, 5), dim3(32, 8)>>>(
        qkv_w, proj_w, ffn_w1, ffn_w2, conv_w, qkvT, projT, ffn1T, ffn2T, wcT);

    // conv as GEMM, split-K=2: per (batch,split) M=2048, N=512, Ksub=768
    hgemm_kernel<1, 2><<<dim3(4, 16, 4), 256, GEMM_SMEM>>>(
        xpad, CDIM, (long long)(T_SEQ + 2) * CDIM,
        wcT, 3 * CDIM,
        convh, CDIM, (long long)T_SEQ * CDIM, HBUF,
        768, conv_b);

    // x1 = LN(x + conv1 + conv2)
    add_ln_kernel<1, 0, 1><<<BT / 2, 256>>>(x, convh, g1, b1, x1h);

    // qkv: M=4096, N=1536, K=512 (384 CTAs, unsplit)
    hgemm_kernel<1, 1><<<dim3(12, 32, 1), 256, GEMM_SMEM>>>(
        x1h, CDIM, 0, qkvT, CDIM, qkvh, 3 * CDIM, 0, 0, CDIM, qkv_b);

    // fp16 causal flash attention (unnormalized exp)
    flash_attn_h_kernel<<<dim3(T_SEQ / 64, BDIM * HNUM), 128>>>(qkvh, attnh);

    // proj, split-K=2: N=512, Ksub=256
    hgemm_kernel<1, 2><<<dim3(4, 32, 2), 256, GEMM_SMEM>>>(
        attnh, CDIM, 0, projT, CDIM, projh, CDIM, 0, HBUF, 256, proj_b);

    // x2 = LN(x1 + proj1 + proj2)
    add_ln_kernel<0, 0, 1><<<BT / 2, 256>>>(x1h, projh, g2, b2, x2h);

    // ffn1: M=4096, N=1024, K=512, relu (256 CTAs, unsplit)
    hgemm_kernel<2, 1><<<dim3(8, 32, 1), 256, GEMM_SMEM>>>(
        x2h, CDIM, 0, ffn1T, CDIM, ffnhh, 2 * CDIM, 0, 0, CDIM, ffn_b1);

    // ffn2, split-K=2: N=512, Ksub=512
    hgemm_kernel<1, 2><<<dim3(4, 32, 2), 256, GEMM_SMEM>>>(
        ffnhh, 2 * CDIM, 0, ffn2T, 2 * CDIM, ffn2h, CDIM, 0, HBUF, 512, ffn_b2);

    // out = LN(x2 + ffn_1 + ffn_2), fp32 out
    add_ln_kernel<0, 1, 1><<<BT / 2, 256>>>(x2h, ffn2h, g3, b3, out);
}

// round 16
// speedup vs baseline: 1.0033x; 1.0033x over previous
#include <cuda_runtime.h>
#include <cuda_fp16.h>
#include <cstdint>

// Problem constants
#define T_SEQ 2048
#define CDIM  512
#define BDIM  2
#define HNUM  8
#define HD    64
#define BT    (BDIM * T_SEQ)

// ---------------- scratch (device globals; no allocation allowed) ----------
__device__ __half g_xpad [BDIM * (T_SEQ + 2) * CDIM];
__device__ __half g_wcT  [CDIM * 3 * CDIM];     // [o][k*512+i]
__device__ __half g_qkvT [3 * CDIM * CDIM];
__device__ __half g_projT[CDIM * CDIM];
__device__ __half g_ffn1T[2 * CDIM * CDIM];
__device__ __half g_ffn2T[CDIM * 2 * CDIM];
__device__ __half g_convh[BT * CDIM];
__device__ __half g_x1h  [BT * CDIM];
__device__ __half g_x2h  [BT * CDIM];
__device__ __half g_qkvh [BT * 3 * CDIM];
__device__ __half g_attnh[BT * CDIM];
__device__ __half g_projh[BT * CDIM];
__device__ __half g_ffnhh[BT * 2 * CDIM];
__device__ __half g_ffn2h[BT * CDIM];

// ---------------- small prep kernels ---------------------------------------
__global__ void pad_kernel(const float* __restrict__ x, __half* __restrict__ xpad) {
    int idx = blockIdx.x * blockDim.x + threadIdx.x;
    const int total = BDIM * (T_SEQ + 2) * CDIM;
    if (idx >= total) return;
    int c = idx % CDIM;
    int t = (idx / CDIM) % (T_SEQ + 2);
    int b = idx / (CDIM * (T_SEQ + 2));
    float v = (t < 2) ? 0.0f : x[((long long)b * T_SEQ + (t - 2)) * CDIM + c];
    xpad[idx] = __float2half_rn(v);
}

// all weight preps in one launch: z=0..3 tiled transposes, z=4 conv gather.
__global__ void prep_weights_kernel(const float* __restrict__ qkv_w,
                                    const float* __restrict__ proj_w,
                                    const float* __restrict__ ffn_w1,
                                    const float* __restrict__ ffn_w2,
                                    const float* __restrict__ conv_w,
                                    __half* __restrict__ qkvT,
                                    __half* __restrict__ projT,
                                    __half* __restrict__ ffn1T,
                                    __half* __restrict__ ffn2T,
                                    __half* __restrict__ wcT) {
    if (blockIdx.z == 4) {
        int r = blockIdx.x * 32 + threadIdx.x;       // 0..1535
        int o0 = blockIdx.y * 32;
        if (o0 >= CDIM) return;
        int k = r / CDIM;
        int i = r % CDIM;
        #pragma unroll
        for (int j = 0; j < 32; j += 8) {
            int o = o0 + threadIdx.y + j;
            wcT[(long long)o * (3 * CDIM) + r] =
                __float2half_rn(conv_w[((long long)o * CDIM + i) * 3 + k]);
        }
        return;
    }
    const float* in;
    __half* outp;
    int K, N;
    switch (blockIdx.z) {
        case 0: in = qkv_w;  outp = qkvT;  K = 512;  N = 1536; break;
        case 1: in = proj_w; outp = projT; K = 512;  N = 512;  break;
        case 2: in = ffn_w1; outp = ffn1T; K = 512;  N = 1024; break;
        default: in = ffn_w2; outp = ffn2T; K = 1024; N = 512; break;
    }
    int bx = blockIdx.x * 32, by = blockIdx.y * 32;
    if (bx >= N || by >= K) return;

    __shared__ float tile[32][33];
    #pragma unroll
    for (int j = 0; j < 32; j += 8)
        tile[threadIdx.y + j][threadIdx.x] =
            in[(long long)(by + threadIdx.y + j) * N + bx + threadIdx.x];
    __syncthreads();
    #pragma unroll
    for (int j = 0; j < 32; j += 8)
        outp[(long long)(bx + threadIdx.y + j) * K + by + threadIdx.x] =
            __float2half_rn(tile[threadIdx.x][threadIdx.y + j]);
}

// ---------------- fused residual add + LayerNorm (fp16 dataflow) -------------
template <int A_FP32, int OUT_FP32>
__global__ void add_ln_kernel(const void* __restrict__ av, const __half* __restrict__ r,
                              const float* __restrict__ g, const float* __restrict__ be,
                              void* __restrict__ outv) {
    __shared__ float sh[8];
    const int tid = threadIdx.x;
    const int half = tid >> 7;
    const int t2 = tid & 127;
    const long long row = (long long)blockIdx.x * 2 + half;

    float a0, a1, a2, a3;
    if (A_FP32) {
        const float4 va = ((const float4*)((const float*)av + row * CDIM))[t2];
        a0 = va.x; a1 = va.y; a2 = va.z; a3 = va.w;
    } else {
        uint2 u = *(const uint2*)((const __half*)av + row * CDIM + t2 * 4);
        __half2 h0 = *(__half2*)&u.x;
        __half2 h1 = *(__half2*)&u.y;
        a0 = __low2float(h0); a1 = __high2float(h0);
        a2 = __low2float(h1); a3 = __high2float(h1);
    }
    float r0, r1, r2, r3;
    {
        uint2 u = *(const uint2*)(r + row * CDIM + t2 * 4);
        __half2 h0 = *(__half2*)&u.x;
        __half2 h1 = *(__half2*)&u.y;
        r0 = __low2float(h0); r1 = __high2float(h0);
        r2 = __low2float(h1); r3 = __high2float(h1);
    }
    float x0 = a0 + r0, x1 = a1 + r1, x2 = a2 + r2, x3 = a3 + r3;

    float s = x0 + x1 + x2 + x3;
    #pragma unroll
    for (int o = 16; o; o >>= 1) s += __shfl_xor_sync(0xffffffffu, s, o);
    if ((t2 & 31) == 0) sh[half * 4 + (t2 >> 5)] = s;
    __syncthreads();
    float mean = (sh[half * 4] + sh[half * 4 + 1] + sh[half * 4 + 2] + sh[half * 4 + 3])
                 * (1.0f / CDIM);
    __syncthreads();

    float d0 = x0 - mean, d1 = x1 - mean, d2 = x2 - mean, d3 = x3 - mean;
    float ss = d0 * d0 + d1 * d1 + d2 * d2 + d3 * d3;
    #pragma unroll
    for (int o = 16; o; o >>= 1) ss += __shfl_xor_sync(0xffffffffu, ss, o);
    if ((t2 & 31) == 0) sh[half * 4 + (t2 >> 5)] = ss;
    __syncthreads();
    float var = (sh[half * 4] + sh[half * 4 + 1] + sh[half * 4 + 2] + sh[half * 4 + 3])
                * (1.0f / CDIM);
    float rs = rsqrtf(var + 1e-5f);

    float4 vg = ((const float4*)g)[t2];
    float4 vb = ((const float4*)be)[t2];
    float o0 = d0 * rs * vg.x + vb.x;
    float o1 = d1 * rs * vg.y + vb.y;
    float o2 = d2 * rs * vg.z + vb.z;
    float o3 = d3 * rs * vg.w + vb.w;

    if (OUT_FP32) {
        ((float4*)((float*)outv + row * CDIM))[t2] = make_float4(o0, o1, o2, o3);
    } else {
        __half2 h0 = __floats2half2_rn(o0, o1);
        __half2 h1 = __floats2half2_rn(o2, o3);
        *(uint2*)((__half*)outv + row * CDIM + t2 * 4) =
            make_uint2(*(uint32_t*)&h0, *(uint32_t*)&h1);
    }
}

// ---------------- mma / ldmatrix helpers -------------------------------------
__device__ __forceinline__ void mma_f16(float c[4], uint32_t a0, uint32_t a1,
                                        uint32_t a2, uint32_t a3,
                                        uint32_t b0, uint32_t b1) {
    asm volatile(
        "mma.sync.aligned.m16n8k16.row.col.f32.f16.f16.f32 "
        "{%0,%1,%2,%3}, {%4,%5,%6,%7}, {%8,%9}, {%0,%1,%2,%3};"
        : "+f"(c[0]), "+f"(c[1]), "+f"(c[2]), "+f"(c[3])
        : "r"(a0), "r"(a1), "r"(a2), "r"(a3), "r"(b0), "r"(b1));
}

__device__ __forceinline__ void ldsm_x4(uint32_t& r0, uint32_t& r1,
                                        uint32_t& r2, uint32_t& r3, uint32_t addr) {
    asm volatile("ldmatrix.sync.aligned.m8n8.x4.shared.b16 {%0,%1,%2,%3}, [%4];"
                 : "=r"(r0), "=r"(r1), "=r"(r2), "=r"(r3) : "r"(addr));
}

#define CP16(dst, src) \
    asm volatile("cp.async.cg.shared.global [%0], [%1], 16;" :: "r"(dst), "l"(src))
#define CP_COMMIT() asm volatile("cp.async.commit_group;")
#define CP_WAIT(n)  asm volatile("cp.async.wait_group %0;" :: "n"(n))

// ---------------- fp16 TC GEMM: 128x128 tile, BK=64, 2-stage -> 2 CTAs/SM ----
// GSTAGES=2 (73.7KB smem) is the only change vs the 210.9us best: two CTAs
// now genuinely co-reside per SM, covering each other's wait/sync bubbles.
#define RBYTES 144
#define ABYTES (128 * RBYTES)         // 18432 B
#define STG_BYTES (2 * ABYTES)        // 36864 B
#define GSTAGES 2
#define GEMM_SMEM (GSTAGES * STG_BYTES)   // 73728 B

__device__ __forceinline__ void load_tile_h(uint32_t sbase,
                                            const __half* __restrict__ gA, int lda,
                                            const __half* __restrict__ gB, int ldb,
                                            int tid) {
    #pragma unroll
    for (int i = 0; i < 4; i++) {
        int u = tid + i * 256;
        int row = u >> 3, c = u & 7;
        CP16(sbase + row * RBYTES + c * 16, gA + (long long)row * lda + c * 8);
    }
    #pragma unroll
    for (int i = 0; i < 4; i++) {
        int u = tid + i * 256;
        int row = u >> 3, c = u & 7;
        CP16(sbase + ABYTES + row * RBYTES + c * 16, gB + (long long)row * ldb + c * 8);
    }
}

template <int ACT>   // 1 = +bias, 2 = relu(+bias)
__global__ __launch_bounds__(256, 2)
void hgemm_kernel(const __half* __restrict__ A, int lda, long long strideA,
                  const __half* __restrict__ Bt, int ldb,
                  __half* __restrict__ C, int ldc, long long strideC,
                  int K, const float* __restrict__ bias) {
    A += (long long)blockIdx.z * strideA;
    C += (long long)blockIdx.z * strideC;

    extern __shared__ __half smh[];
    const int tid = threadIdx.x;
    const int lane = tid & 31;
    const int warp = tid >> 5;
    const int warpM = warp >> 2;
    const int warpN = warp & 3;
    const int tg = lane & 3;
    const int gid = lane >> 2;

    uint32_t sbase;
    asm("{ .reg .u64 t; cvta.to.shared.u64 t, %1; cvt.u32.u64 %0, t; }"
        : "=r"(sbase) : "l"(smh));

    float acc[4][4][4];
    #pragma unroll
    for (int i = 0; i < 4; i++)
        #pragma unroll
        for (int j = 0; j < 4; j++)
            #pragma unroll
            for (int q = 0; q < 4; q++) acc[i][j][q] = 0.0f;

    const int aRow = (lane & 15);
    const int aKoff = (lane >> 4) << 4;
    const int bLocal = lane & 7;
    const int bSel = (lane >> 3) & 3;
    const int bNsub = (bSel >> 1);
    const int bKoff = (bSel & 1) * 16;

    const __half* Ag = A + (long long)blockIdx.y * 128 * lda;
    const __half* Bg = Bt + (long long)blockIdx.x * 128 * ldb;
    const int ntile = K >> 6;

    // prologue: fill stage 0
    load_tile_h(sbase, Ag, lda, Bg, ldb, tid);
    CP_COMMIT();

    for (int t = 0; t < ntile; t++) {
        CP_WAIT(0);
        __syncthreads();

        int f = t + 1;
        if (f < ntile)
            load_tile_h(sbase + (f & 1) * STG_BYTES, Ag + f * 64, lda,
                        Bg + f * 64, ldb, tid);
        CP_COMMIT();

        const uint32_t Ab = sbase + (t & 1) * STG_BYTES;
        const uint32_t Bb = Ab + ABYTES;

        #pragma unroll
        for (int ks = 0; ks < 4; ks++) {
            const int kbB = ks * 32;
            uint32_t af[4][4], bf[4][2];
            #pragma unroll
            for (int mi = 0; mi < 4; mi++) {
                uint32_t addr = Ab + (warpM * 64 + mi * 16 + aRow) * RBYTES + kbB + aKoff;
                ldsm_x4(af[mi][0], af[mi][1], af[mi][2], af[mi][3], addr);
            }
            #pragma unroll
            for (int p = 0; p < 2; p++) {
                uint32_t addr = Bb + (warpN * 32 + (2 * p + bNsub) * 8 + bLocal) * RBYTES
                                + kbB + bKoff;
                ldsm_x4(bf[2 * p][0], bf[2 * p][1], bf[2 * p + 1][0], bf[2 * p + 1][1], addr);
            }
            #pragma unroll
            for (int mi = 0; mi < 4; mi++)
                #pragma unroll
                for (int ni = 0; ni < 4; ni++)
                    mma_f16(acc[mi][ni], af[mi][0], af[mi][1], af[mi][2], af[mi][3],
                            bf[ni][0], bf[ni][1]);
        }
        __syncthreads();
    }

    const int mbase = blockIdx.y * 128 + warpM * 64;
    const int nbase = blockIdx.x * 128 + warpN * 32;
    #pragma unroll
    for (int ni = 0; ni < 4; ni++) {
        int c0 = nbase + ni * 8 + tg * 2;
        float bv0 = 0.0f, bv1 = 0.0f;
        if (ACT > 0) { bv0 = bias[c0]; bv1 = bias[c0 + 1]; }
        #pragma unroll
        for (int mi = 0; mi < 4; mi++) {
            int r0 = mbase + mi * 16 + gid;
            float v00 = acc[mi][ni][0] + bv0;
            float v01 = acc[mi][ni][1] + bv1;
            float v10 = acc[mi][ni][2] + bv0;
            float v11 = acc[mi][ni][3] + bv1;
            if (ACT == 2) {
                v00 = fmaxf(v00, 0.0f); v01 = fmaxf(v01, 0.0f);
                v10 = fmaxf(v10, 0.0f); v11 = fmaxf(v11, 0.0f);
            }
            *(__half2*)(C + (long long)r0 * ldc + c0) = __floats2half2_rn(v00, v01);
            *(__half2*)(C + (long long)(r0 + 8) * ldc + c0) = __floats2half2_rn(v10, v11);
        }
    }
}

// ---------------- fp16 flash attention (BQ=64, unnormalized exp) -------------
#define KS_STRIDE 72
#define VT_STRIDE 76

__global__ __launch_bounds__(128)
void flash_attn_h_kernel(const __half* __restrict__ qkv, __half* __restrict__ out) {
    __shared__ __half Ks[64 * KS_STRIDE];
    __shared__ __half Vt[64 * VT_STRIDE];

    const int qb = (gridDim.x - 1) - blockIdx.x;
    const int bh = blockIdx.y;
    const int b = bh >> 3, h = bh & 7;
    const int tid = threadIdx.x;
    const int lane = tid & 31;
    const int warp = tid >> 5;
    const int g = lane >> 2;
    const int t = lane & 3;
    const long long rstride = 3 * CDIM;

    const __half* q0 = qkv + ((long long)(b * T_SEQ + qb * 64 + warp * 16)) * rstride + h * HD;
    const __half2 scale = __float2half2_rn(0.125f);
    uint32_t qf[4][4];
    #pragma unroll
    for (int ks = 0; ks < 4; ks++) {
        __half2 v0 = __hmul2(*(const __half2*)(q0 + (long long)g * rstride + ks * 16 + 2 * t), scale);
        __half2 v1 = __hmul2(*(const __half2*)(q0 + (long long)(g + 8) * rstride + ks * 16 + 2 * t), scale);
        __half2 v2 = __hmul2(*(const __half2*)(q0 + (long long)g * rstride + ks * 16 + 8 + 2 * t), scale);
        __half2 v3 = __hmul2(*(const __half2*)(q0 + (long long)(g + 8) * rstride + ks * 16 + 8 + 2 * t), scale);
        qf[ks][0] = *(uint32_t*)&v0;
        qf[ks][1] = *(uint32_t*)&v1;
        qf[ks][2] = *(uint32_t*)&v2;
        qf[ks][3] = *(uint32_t*)&v3;
    }

    float o[8][4];
    #pragma unroll
    for (int ni = 0; ni < 8; ni++)
        #pragma unroll
        for (int q = 0; q < 4; q++) o[ni][q] = 0.0f;
    float ls0 = 0.0f, ls1 = 0.0f;

    const int row0 = qb * 64 + warp * 16 + g;
    const int row1 = row0 + 8;

    for (int kb = 0; kb <= qb; kb++) {
        const __half* kbase = qkv + ((long long)(b * T_SEQ + kb * 64)) * rstride + CDIM + h * HD;
        const __half* vbase = kbase + CDIM;

        #pragma unroll
        for (int i = 0; i < 4; i++) {
            int u = tid + i * 128;
            int r = u >> 3, c = u & 7;
            *(uint4*)&Ks[r * KS_STRIDE + c * 8] =
                *(const uint4*)(kbase + (long long)r * rstride + c * 8);
        }
        #pragma unroll
        for (int i = 0; i < 2; i++) {
            int u = tid + i * 128;
            int kp = u >> 3, d8 = u & 7;
            uint4 va = *(const uint4*)(vbase + (long long)(2 * kp) * rstride + d8 * 8);
            uint4 vb = *(const uint4*)(vbase + (long long)(2 * kp + 1) * rstride + d8 * 8);
            const __half* ah = (const __half*)&va;
            const __half* bhp = (const __half*)&vb;
            #pragma unroll
            for (int j = 0; j < 8; j++)
                *(__half2*)&Vt[(d8 * 8 + j) * VT_STRIDE + 2 * kp] =
                    __halves2half2(ah[j], bhp[j]);
        }
        __syncthreads();

        float s[8][4];
        #pragma unroll
        for (int ni = 0; ni < 8; ni++) {
            s[ni][0] = s[ni][1] = s[ni][2] = s[ni][3] = 0.0f;
            const __half* kr = &Ks[(ni * 8 + g) * KS_STRIDE];
            #pragma unroll
            for (int ks = 0; ks < 4; ks++) {
                uint32_t b0 = *(const uint32_t*)(kr + ks * 16 + 2 * t);
                uint32_t b1 = *(const uint32_t*)(kr + ks * 16 + 8 + 2 * t);
                mma_f16(s[ni], qf[ks][0], qf[ks][1], qf[ks][2], qf[ks][3], b0, b1);
            }
        }

        if (kb == qb) {
            #pragma unroll
            for (int ni = 0; ni < 8; ni++) {
                int col = kb * 64 + ni * 8 + 2 * t;
                if (col > row0)     s[ni][0] = -1e30f;
                if (col + 1 > row0) s[ni][1] = -1e30f;
                if (col > row1)     s[ni][2] = -1e30f;
                if (col + 1 > row1) s[ni][3] = -1e30f;
            }
        }

        uint32_t pf[4][4];
        #pragma unroll
        for (int j = 0; j < 4; j++) {
            float p00 = __expf(s[2 * j][0]);
            float p01 = __expf(s[2 * j][1]);
            float p02 = __expf(s[2 * j][2]);
            float p03 = __expf(s[2 * j][3]);
            float p10 = __expf(s[2 * j + 1][0]);
            float p11 = __expf(s[2 * j + 1][1]);
            float p12 = __expf(s[2 * j + 1][2]);
            float p13 = __expf(s[2 * j + 1][3]);
            ls0 += p00 + p01 + p10 + p11;
            ls1 += p02 + p03 + p12 + p13;
            __half2 h0 = __floats2half2_rn(p00, p01);
            __half2 h1 = __floats2half2_rn(p02, p03);
            __half2 h2 = __floats2half2_rn(p10, p11);
            __half2 h3 = __floats2half2_rn(p12, p13);
            pf[j][0] = *(uint32_t*)&h0;
            pf[j][1] = *(uint32_t*)&h1;
            pf[j][2] = *(uint32_t*)&h2;
            pf[j][3] = *(uint32_t*)&h3;
        }

        #pragma unroll
        for (int ni = 0; ni < 8; ni++) {
            const __half* vr = &Vt[(ni * 8 + g) * VT_STRIDE];
            #pragma unroll
            for (int j = 0; j < 4; j++) {
                uint32_t b0 = *(const uint32_t*)(vr + j * 16 + 2 * t);
                uint32_t b1 = *(const uint32_t*)(vr + j * 16 + 8 + 2 * t);
                mma_f16(o[ni], pf[j][0], pf[j][1], pf[j][2], pf[j][3], b0, b1);
            }
        }
        __syncthreads();
    }

    ls0 += __shfl_xor_sync(0xffffffffu, ls0, 1);
    ls0 += __shfl_xor_sync(0xffffffffu, ls0, 2);
    ls1 += __shfl_xor_sync(0xffffffffu, ls1, 1);
    ls1 += __shfl_xor_sync(0xffffffffu, ls1, 2);
    float inv0 = 1.0f / ls0, inv1 = 1.0f / ls1;
    __half* obase = out + ((long long)(b * T_SEQ)) * CDIM + h * HD;
    #pragma unroll
    for (int ni = 0; ni < 8; ni++) {
        int col = ni * 8 + 2 * t;
        *(__half2*)(obase + (long long)row0 * CDIM + col) =
            __floats2half2_rn(o[ni][0] * inv0, o[ni][1] * inv0);
        *(__half2*)(obase + (long long)row1 * CDIM + col) =
            __floats2half2_rn(o[ni][2] * inv1, o[ni][3] * inv1);
    }
}

// ---------------- launch -----------------------------------------------------
extern "C" void kernel_launch(void* const* d_in, const int* in_sizes, int n_in,
                              void* d_out, int out_size) {
    const float* x      = (const float*)d_in[0];
    const float* conv_w = (const float*)d_in[1];
    const float* conv_b = (const float*)d_in[2];
    const float* g1     = (const float*)d_in[3];
    const float* b1     = (const float*)d_in[4];
    const float* qkv_w  = (const float*)d_in[5];
    const float* qkv_b  = (const float*)d_in[6];
    const float* proj_w = (const float*)d_in[7];
    const float* proj_b = (const float*)d_in[8];
    const float* g2     = (const float*)d_in[9];
    const float* b2     = (const float*)d_in[10];
    const float* ffn_w1 = (const float*)d_in[11];
    const float* ffn_b1 = (const float*)d_in[12];
    const float* ffn_w2 = (const float*)d_in[13];
    const float* ffn_b2 = (const float*)d_in[14];
    const float* g3     = (const float*)d_in[15];
    const float* b3     = (const float*)d_in[16];
    float* out = (float*)d_out;

    __half *xpad, *wcT, *qkvT, *projT, *ffn1T, *ffn2T;
    __half *convh, *x1h, *x2h, *qkvh, *attnh, *projh, *ffnhh, *ffn2h;
    cudaGetSymbolAddress((void**)&xpad,  g_xpad);
    cudaGetSymbolAddress((void**)&wcT,   g_wcT);
    cudaGetSymbolAddress((void**)&qkvT,  g_qkvT);
    cudaGetSymbolAddress((void**)&projT, g_projT);
    cudaGetSymbolAddress((void**)&ffn1T, g_ffn1T);
    cudaGetSymbolAddress((void**)&ffn2T, g_ffn2T);
    cudaGetSymbolAddress((void**)&convh, g_convh);
    cudaGetSymbolAddress((void**)&x1h,   g_x1h);
    cudaGetSymbolAddress((void**)&x2h,   g_x2h);
    cudaGetSymbolAddress((void**)&qkvh,  g_qkvh);
    cudaGetSymbolAddress((void**)&attnh, g_attnh);
    cudaGetSymbolAddress((void**)&projh, g_projh);
    cudaGetSymbolAddress((void**)&ffnhh, g_ffnhh);
    cudaGetSymbolAddress((void**)&ffn2h, g_ffn2h);

    cudaFuncSetAttribute(hgemm_kernel<1>,
                         cudaFuncAttributeMaxDynamicSharedMemorySize, GEMM_SMEM);
    cudaFuncSetAttribute(hgemm_kernel<2>,
                         cudaFuncAttributeMaxDynamicSharedMemorySize, GEMM_SMEM);

    {
        int total = BDIM * (T_SEQ + 2) * CDIM;
        pad_kernel<<<(total + 255) / 256, 256>>>(x, xpad);
    }
    prep_weights_kernel<<<dim3(48, 32, 5), dim3(32, 8)>>>(
        qkv_w, proj_w, ffn_w1, ffn_w2, conv_w, qkvT, projT, ffn1T, ffn2T, wcT);

    // conv as GEMM: per batch M=2048, N=512, K=1536 (overlapping A rows)
    hgemm_kernel<1><<<dim3(4, 16, 2), 256, GEMM_SMEM>>>(
        xpad, CDIM, (long long)(T_SEQ + 2) * CDIM,
        wcT, 3 * CDIM,
        convh, CDIM, (long long)T_SEQ * CDIM,
        3 * CDIM, conv_b);

    // x1 = LN(x + conv): fp32 a, fp16 out
    add_ln_kernel<1, 0><<<BT / 2, 256>>>(x, convh, g1, b1, x1h);

    // qkv: M=4096, N=1536, K=512
    hgemm_kernel<1><<<dim3(12, 32, 1), 256, GEMM_SMEM>>>(
        x1h, CDIM, 0, qkvT, CDIM, qkvh, 3 * CDIM, 0, CDIM, qkv_b);

    // fp16 causal flash attention (unnormalized exp)
    flash_attn_h_kernel<<<dim3(T_SEQ / 64, BDIM * HNUM), 128>>>(qkvh, attnh);

    // proj: M=4096, N=512, K=512
    hgemm_kernel<1><<<dim3(4, 32, 1), 256, GEMM_SMEM>>>(
        attnh, CDIM, 0, projT, CDIM, projh, CDIM, 0, CDIM, proj_b);

    // x2 = LN(x1 + proj): fp16 a, fp16 out
    add_ln_kernel<0, 0><<<BT / 2, 256>>>(x1h, projh, g2, b2, x2h);

    // ffn1: M=4096, N=1024, K=512, relu
    hgemm_kernel<2><<<dim3(8, 32, 1), 256, GEMM_SMEM>>>(
        x2h, CDIM, 0, ffn1T, CDIM, ffnhh, 2 * CDIM, 0, CDIM, ffn_b1);

    // ffn2: M=4096, N=512, K=1024
    hgemm_kernel<1><<<dim3(4, 32, 1), 256, GEMM_SMEM>>>(
        ffnhh, 2 * CDIM, 0, ffn2T, 2 * CDIM, ffn2h, CDIM, 0, 2 * CDIM, ffn_b2);

    // out = LN(x2 + ffn): fp16 a, fp32 out
    add_ln_kernel<0, 1><<<BT / 2, 256>>>(x2h, ffn2h, g3, b3, out);
}